// round 2
// baseline (speedup 1.0000x reference)
#include <cuda_runtime.h>

// DenseEnergyLoss: N=4, K=21, H=W=128, SCALE=0.5 -> oh=ow=64, P=4096.
// out = -0.05 * S / (N*P),
// S = sum_{n,p,q} gate[n,p] * exp(-0.5*||f_p-f_q||^2) * sum_k seg_m[n,k,p]*seg_m[n,k,q]

#define NB   4
#define KC   21
#define HH   128
#define WW   128
#define OHW  64
#define PTOT 4096          // OHW*OHW
#define PT   256           // p per block (1 per thread)
#define QT   256           // q tile in smem
#define NPT  (PTOT/PT)     // 16
#define NQT  (PTOT/QT)     // 16
#define NBLK (NPT*NQT*NB)  // 1024
#define D2_CUT 36.0f       // exp(-18)=1.5e-8 -> skipped mass < 1e-4 relative

__device__ float g_feat[NB][5][PTOT];   // [n][dim][p]
__device__ float g_seg [NB][KC][PTOT];  // seg_m
__device__ float g_gate[NB][PTOT];
__device__ float g_part[NBLK];

// ---------------------------------------------------------------------------
// Phase 1: downsample + features + gate.  2:1 half-pixel bilinear == 2x2 mean,
// nearest == stride-2 pick at (2y,2x).
// ---------------------------------------------------------------------------
__global__ void prep_kernel(const float* __restrict__ img,
                            const float* __restrict__ seg,
                            const float* __restrict__ roi,
                            const float* __restrict__ lab) {
    int idx = blockIdx.x * blockDim.x + threadIdx.x;   // 0 .. NB*PTOT-1
    int n = idx >> 12;
    int p = idx & (PTOT - 1);
    int y = p >> 6, x = p & 63;
    int yy = 2 * y, xx = 2 * x;

    float segv[KC];
    float maxs = -1e30f;
#pragma unroll
    for (int k = 0; k < KC; k++) {
        const float* b = seg + (((size_t)(n * KC + k) * HH + yy) * WW + xx);
        float s = 0.25f * (b[0] + b[1] + b[WW] + b[WW + 1]);
        segv[k] = s;
        maxs = fmaxf(maxs, s);
    }
    float r  = roi[((size_t)n * HH + yy) * WW + xx];
    float lv = lab[((size_t)n * HH + yy) * WW + xx];
    float gate = ((int)lv == 255) ? 1.0f : (r - maxs);
    gate = fmaxf(gate, 0.0f);

    g_gate[n][p] = gate;
#pragma unroll
    for (int k = 0; k < KC; k++) g_seg[n][k][p] = segv[k] * r;

    g_feat[n][0][p] = (float)x * (1.0f / 40.0f);   // SIGMA_XY * SCALE = 40
    g_feat[n][1][p] = (float)y * (1.0f / 40.0f);
#pragma unroll
    for (int c = 0; c < 3; c++)
        g_feat[n][2 + c][p] =
            img[(((size_t)(n * 3 + c)) * HH + yy) * WW + xx] * (1.0f / 15.0f);
}

// ---------------------------------------------------------------------------
// Phase 2: pair loop. Each thread owns one p; q tiled through smem.
// acc_p = sum_q exp(-0.5 d2) * dot_k ; multiply by gate[p] at the end.
// ---------------------------------------------------------------------------
__global__ __launch_bounds__(PT) void pair_kernel() {
    __shared__ float sf[5][QT];
    __shared__ float ss[KC][QT];
    __shared__ float red[PT / 32];

    int t  = threadIdx.x;
    int n  = blockIdx.z;
    int q0 = blockIdx.y * QT;
    int p  = blockIdx.x * PT + t;

#pragma unroll
    for (int c = 0; c < 5; c++)  sf[c][t] = g_feat[n][c][q0 + t];
#pragma unroll
    for (int k = 0; k < KC; k++) ss[k][t] = g_seg[n][k][q0 + t];
    __syncthreads();

    float fp0 = g_feat[n][0][p];
    float fp1 = g_feat[n][1][p];
    float fp2 = g_feat[n][2][p];
    float fp3 = g_feat[n][3][p];
    float fp4 = g_feat[n][4][p];
    float sp[KC];
#pragma unroll
    for (int k = 0; k < KC; k++) sp[k] = g_seg[n][k][p];
    float gp = g_gate[n][p];

    float acc = 0.0f;
#pragma unroll 4
    for (int j = 0; j < QT; j++) {
        float d0 = fp0 - sf[0][j];
        float d1 = fp1 - sf[1][j];
        float d2 = fp2 - sf[2][j];
        float d3 = fp3 - sf[3][j];
        float d4 = fp4 - sf[4][j];
        float dd = d0 * d0 + d1 * d1 + d2 * d2 + d3 * d3 + d4 * d4;
        if (dd < D2_CUT) {
            float w = __expf(-0.5f * dd);
            float dot = 0.0f;
#pragma unroll
            for (int k = 0; k < KC; k++) dot += sp[k] * ss[k][j];
            acc += w * dot;
        }
    }
    acc *= gp;

    // deterministic block reduction
#pragma unroll
    for (int o = 16; o > 0; o >>= 1)
        acc += __shfl_down_sync(0xffffffffu, acc, o);
    if ((t & 31) == 0) red[t >> 5] = acc;
    __syncthreads();
    if (t == 0) {
        float s = 0.0f;
#pragma unroll
        for (int w = 0; w < PT / 32; w++) s += red[w];
        g_part[((size_t)blockIdx.z * gridDim.y + blockIdx.y) * gridDim.x + blockIdx.x] = s;
    }
}

// ---------------------------------------------------------------------------
// Phase 3: fixed-order reduction of the 1024 partials.
// ---------------------------------------------------------------------------
__global__ void final_kernel(float* __restrict__ out) {
    __shared__ float red[8];
    int t = threadIdx.x;  // 256
    float v = 0.0f;
    for (int i = t; i < NBLK; i += 256) v += g_part[i];
#pragma unroll
    for (int o = 16; o > 0; o >>= 1)
        v += __shfl_down_sync(0xffffffffu, v, o);
    if ((t & 31) == 0) red[t >> 5] = v;
    __syncthreads();
    if (t == 0) {
        float s = 0.0f;
#pragma unroll
        for (int w = 0; w < 8; w++) s += red[w];
        // out = WEIGHT * (-0.5) * S / (N*P) = -0.05 * S / 16384
        out[0] = s * (-0.05f / 16384.0f);
    }
}

extern "C" void kernel_launch(void* const* d_in, const int* in_sizes, int n_in,
                              void* d_out, int out_size) {
    const float* img = (const float*)d_in[0];   // (4,3,128,128)
    const float* seg = (const float*)d_in[1];   // (4,21,128,128)
    const float* roi = (const float*)d_in[2];   // (4,128,128)
    const float* lab = (const float*)d_in[3];   // (4,1,128,128)
    float* out = (float*)d_out;

    prep_kernel<<<(NB * PTOT) / 256, 256>>>(img, seg, roi, lab);
    dim3 grid(NPT, NQT, NB);
    pair_kernel<<<grid, PT>>>();
    final_kernel<<<1, 256>>>(out);
}

// round 3
// speedup vs baseline: 2.0823x; 2.0823x over previous
#include <cuda_runtime.h>

// DenseEnergyLoss, exact (no cutoff), symmetric-pair formulation.
// S = sum_{p<q}(g_p+g_q)*A(p,q)*dot(p,q) + sum_p g_p*dot(p,p),  A=exp(-0.5 d2)
// out = -0.05 * S / 16384

#define NB   4
#define KC   21
#define HH   128
#define WW   128
#define PTOT 4096
#define PT   256
#define QT   256
#define NPT  (PTOT/PT)          // 16
#define NTRI (NPT*(NPT+1)/2)    // 136 tile pairs per image
#define NBLK (NTRI*NB)          // 544

#define LOG2E 1.4426950408889634f
#define CNEG  (-0.5f*LOG2E)

__device__ float g_feat[NB][5][PTOT];   // features /sigma
__device__ float g_seg [NB][KC][PTOT];  // seg * roi
__device__ float g_gate[NB][PTOT];
__device__ float g_a0  [NB][PTOT];      // CNEG * |f|^2
__device__ float g_s2  [NB][PTOT];      // sum_k seg^2  (self dot)
__device__ float g_part[NBLK];

__device__ __forceinline__ float ex2(float x) {
    float y; asm("ex2.approx.f32 %0, %1;" : "=f"(y) : "f"(x)); return y;
}

// ---------------------------------------------------------------------------
__global__ void prep_kernel(const float* __restrict__ img,
                            const float* __restrict__ seg,
                            const float* __restrict__ roi,
                            const float* __restrict__ lab) {
    int idx = blockIdx.x * blockDim.x + threadIdx.x;
    int n = idx >> 12;
    int p = idx & (PTOT - 1);
    int y = p >> 6, x = p & 63;
    int yy = 2 * y, xx = 2 * x;

    float segv[KC];
    float maxs = -1e30f;
#pragma unroll
    for (int k = 0; k < KC; k++) {
        const float* b = seg + (((size_t)(n * KC + k) * HH + yy) * WW + xx);
        float s = 0.25f * (b[0] + b[1] + b[WW] + b[WW + 1]);
        segv[k] = s;
        maxs = fmaxf(maxs, s);
    }
    float r  = roi[((size_t)n * HH + yy) * WW + xx];
    float lv = lab[((size_t)n * HH + yy) * WW + xx];
    float gate = ((int)lv == 255) ? 1.0f : (r - maxs);
    gate = fmaxf(gate, 0.0f);
    g_gate[n][p] = gate;

    float s2 = 0.0f;
#pragma unroll
    for (int k = 0; k < KC; k++) {
        float sm = segv[k] * r;
        g_seg[n][k][p] = sm;
        s2 += sm * sm;
    }
    g_s2[n][p] = s2;

    float f0 = (float)x * (1.0f / 40.0f);   // SIGMA_XY*SCALE = 40
    float f1 = (float)y * (1.0f / 40.0f);
    float f2 = img[(((size_t)(n * 3 + 0)) * HH + yy) * WW + xx] * (1.0f / 15.0f);
    float f3 = img[(((size_t)(n * 3 + 1)) * HH + yy) * WW + xx] * (1.0f / 15.0f);
    float f4 = img[(((size_t)(n * 3 + 2)) * HH + yy) * WW + xx] * (1.0f / 15.0f);
    g_feat[n][0][p] = f0; g_feat[n][1][p] = f1; g_feat[n][2][p] = f2;
    g_feat[n][3][p] = f3; g_feat[n][4][p] = f4;
    g_a0[n][p] = CNEG * (f0*f0 + f1*f1 + f2*f2 + f3*f3 + f4*f4);
}

// ---------------------------------------------------------------------------
// Triangular tile pairs; thread owns p, iterates q-tile in smem.
// ---------------------------------------------------------------------------
__global__ __launch_bounds__(PT) void pair_kernel() {
    __shared__ float ss[QT][28];   // seg q-tile, padded (LDS.128-aligned rows)
    __shared__ float qd[QT][8];    // f0..f4, gq, qc, pad
    __shared__ float red[PT / 32];

    int t = threadIdx.x;
    int n = blockIdx.z;

    // decode triangular tile pair (bp <= bq)
    int idx = blockIdx.x, bp = 0;
    while (idx >= NPT - bp) { idx -= NPT - bp; bp++; }
    int bq = bp + idx;

    int p  = bp * PT + t;
    int q0 = bq * QT;

#pragma unroll
    for (int k = 0; k < KC; k++) ss[t][k] = g_seg[n][k][q0 + t];
#pragma unroll
    for (int c = 0; c < 5; c++)  qd[t][c] = g_feat[n][c][q0 + t];
    qd[t][5] = g_gate[n][q0 + t];
    qd[t][6] = g_a0[n][q0 + t];
    __syncthreads();

    float fp0 = g_feat[n][0][p];
    float fp1 = g_feat[n][1][p];
    float fp2 = g_feat[n][2][p];
    float fp3 = g_feat[n][3][p];
    float fp4 = g_feat[n][4][p];
    float a0p = g_a0[n][p];
    float gp  = g_gate[n][p];
    float sp[KC];
#pragma unroll
    for (int k = 0; k < KC; k++) sp[k] = g_seg[n][k][p];

    bool diag = (bp == bq);
    float accA = diag ? g_s2[n][p] : 0.0f;   // self term (w=1, gate gp only)
    float accB = 0.0f;
    int jstart = diag ? (t + 1) : 0;

#pragma unroll 2
    for (int j = jstart; j < QT; j++) {
        float4 qa = *(const float4*)&qd[j][0];
        float4 qb = *(const float4*)&qd[j][4];
        float dot5 = fp0 * qa.x;
        dot5 = fmaf(fp1, qa.y, dot5);
        dot5 = fmaf(fp2, qa.z, dot5);
        dot5 = fmaf(fp3, qa.w, dot5);
        dot5 = fmaf(fp4, qb.x, dot5);
        float arg = fmaf(LOG2E, dot5, a0p + qb.z);
        float w = ex2(arg);

        float4 s0 = *(const float4*)&ss[j][0];
        float4 s1 = *(const float4*)&ss[j][4];
        float4 s2 = *(const float4*)&ss[j][8];
        float4 s3 = *(const float4*)&ss[j][12];
        float4 s4 = *(const float4*)&ss[j][16];
        float  s20 = ss[j][20];
        float dA = sp[0] * s0.x;
        float dB = sp[1] * s0.y;
        dA = fmaf(sp[2],  s0.z, dA);  dB = fmaf(sp[3],  s0.w, dB);
        dA = fmaf(sp[4],  s1.x, dA);  dB = fmaf(sp[5],  s1.y, dB);
        dA = fmaf(sp[6],  s1.z, dA);  dB = fmaf(sp[7],  s1.w, dB);
        dA = fmaf(sp[8],  s2.x, dA);  dB = fmaf(sp[9],  s2.y, dB);
        dA = fmaf(sp[10], s2.z, dA);  dB = fmaf(sp[11], s2.w, dB);
        dA = fmaf(sp[12], s3.x, dA);  dB = fmaf(sp[13], s3.y, dB);
        dA = fmaf(sp[14], s3.z, dA);  dB = fmaf(sp[15], s3.w, dB);
        dA = fmaf(sp[16], s4.x, dA);  dB = fmaf(sp[17], s4.y, dB);
        dA = fmaf(sp[18], s4.z, dA);  dB = fmaf(sp[19], s4.w, dB);
        dA = fmaf(sp[20], s20,  dA);
        float dot = dA + dB;

        float wd = w * dot;
        accA += wd;                       // * gp at the end
        accB = fmaf(wd, qb.y, accB);      // gate_q side
    }

    float val = fmaf(accA, gp, accB);

#pragma unroll
    for (int o = 16; o > 0; o >>= 1)
        val += __shfl_down_sync(0xffffffffu, val, o);
    if ((t & 31) == 0) red[t >> 5] = val;
    __syncthreads();
    if (t == 0) {
        float s = 0.0f;
#pragma unroll
        for (int w = 0; w < PT / 32; w++) s += red[w];
        g_part[(size_t)blockIdx.z * NTRI + blockIdx.x] = s;
    }
}

// ---------------------------------------------------------------------------
__global__ void final_kernel(float* __restrict__ out) {
    __shared__ float red[8];
    int t = threadIdx.x;  // 256
    float v = 0.0f;
    for (int i = t; i < NBLK; i += 256) v += g_part[i];
#pragma unroll
    for (int o = 16; o > 0; o >>= 1)
        v += __shfl_down_sync(0xffffffffu, v, o);
    if ((t & 31) == 0) red[t >> 5] = v;
    __syncthreads();
    if (t == 0) {
        float s = 0.0f;
#pragma unroll
        for (int w = 0; w < 8; w++) s += red[w];
        out[0] = s * (-0.05f / 16384.0f);
    }
}

extern "C" void kernel_launch(void* const* d_in, const int* in_sizes, int n_in,
                              void* d_out, int out_size) {
    const float* img = (const float*)d_in[0];
    const float* seg = (const float*)d_in[1];
    const float* roi = (const float*)d_in[2];
    const float* lab = (const float*)d_in[3];
    float* out = (float*)d_out;

    prep_kernel<<<(NB * PTOT) / 256, 256>>>(img, seg, roi, lab);
    dim3 grid(NTRI, 1, NB);
    pair_kernel<<<grid, PT>>>();
    final_kernel<<<1, 256>>>(out);
}

// round 4
// speedup vs baseline: 2.5222x; 1.2113x over previous
#include <cuda_runtime.h>

// DenseEnergyLoss, exact, symmetric tiles, packed fp32x2 arithmetic.
// out = -0.05 * S / 16384

#define NB   4
#define KC   21
#define HH   128
#define WW   128
#define PTOT 4096
#define PT   256
#define QT   256
#define NPT  (PTOT/PT)          // 16
#define NTRI (NPT*(NPT+1)/2)    // 136
#define NBLK (NTRI*NB)          // 544

#define LOG2E 1.4426950408889634f
#define CNEG  (-0.5f*LOG2E)

typedef unsigned long long u64;

__device__ float g_raw [NB][KC][PTOT];  // downsampled seg (pre-roi)
__device__ float g_seg [NB][KC][PTOT];  // seg * roi
__device__ float g_feat[NB][5][PTOT];
__device__ float g_gate[NB][PTOT];
__device__ float g_a0  [NB][PTOT];      // CNEG*|f|^2
__device__ float g_part[NBLK];

__device__ __forceinline__ u64 fma2(u64 a, u64 b, u64 c) {
    u64 d; asm("fma.rn.f32x2 %0, %1, %2, %3;" : "=l"(d) : "l"(a), "l"(b), "l"(c)); return d;
}
__device__ __forceinline__ u64 mul2(u64 a, u64 b) {
    u64 d; asm("mul.rn.f32x2 %0, %1, %2;" : "=l"(d) : "l"(a), "l"(b)); return d;
}
__device__ __forceinline__ u64 add2(u64 a, u64 b) {
    u64 d; asm("add.rn.f32x2 %0, %1, %2;" : "=l"(d) : "l"(a), "l"(b)); return d;
}
__device__ __forceinline__ u64 pack2(float lo, float hi) {
    u64 d; asm("mov.b64 %0, {%1, %2};" : "=l"(d) : "f"(lo), "f"(hi)); return d;
}
__device__ __forceinline__ void unpack2(u64 a, float& lo, float& hi) {
    asm("mov.b64 {%0, %1}, %2;" : "=f"(lo), "=f"(hi) : "l"(a));
}
__device__ __forceinline__ float ex2(float x) {
    float y; asm("ex2.approx.f32 %0, %1;" : "=f"(y) : "f"(x)); return y;
}

// ---------------------------------------------------------------------------
// Phase 1a: wide 2x2 box downsample of seg (one thread per (n,k,p)).
// ---------------------------------------------------------------------------
__global__ void prep1_kernel(const float* __restrict__ seg) {
    int idx = blockIdx.x * blockDim.x + threadIdx.x;   // NB*KC*PTOT
    int n = idx / (KC * PTOT);
    int rem = idx - n * (KC * PTOT);
    int k = rem >> 12;
    int p = rem & (PTOT - 1);
    int y = p >> 6, x = p & 63;
    const float2* r0 = (const float2*)(seg + (((size_t)(n * KC + k) * HH + 2 * y) * WW + 2 * x));
    const float2* r1 = r0 + (WW / 2);
    float2 a = r0[0], b = r1[0];
    g_raw[n][k][p] = 0.25f * (a.x + a.y + b.x + b.y);
}

// ---------------------------------------------------------------------------
// Phase 1b: gate, seg*roi, features (raw tile re-read from L2).
// ---------------------------------------------------------------------------
__global__ void prep2_kernel(const float* __restrict__ img,
                             const float* __restrict__ roi,
                             const float* __restrict__ lab) {
    int idx = blockIdx.x * blockDim.x + threadIdx.x;   // NB*PTOT
    int n = idx >> 12;
    int p = idx & (PTOT - 1);
    int y = p >> 6, x = p & 63;
    int yy = 2 * y, xx = 2 * x;

    float rv[KC];
    float maxs = -1e30f;
#pragma unroll
    for (int k = 0; k < KC; k++) {
        float s = g_raw[n][k][p];
        rv[k] = s;
        maxs = fmaxf(maxs, s);
    }
    float r  = roi[((size_t)n * HH + yy) * WW + xx];
    float lv = lab[((size_t)n * HH + yy) * WW + xx];
    float gate = ((int)lv == 255) ? 1.0f : (r - maxs);
    g_gate[n][p] = fmaxf(gate, 0.0f);
#pragma unroll
    for (int k = 0; k < KC; k++) g_seg[n][k][p] = rv[k] * r;

    float f0 = (float)x * (1.0f / 40.0f);
    float f1 = (float)y * (1.0f / 40.0f);
    float f2 = img[(((size_t)(n * 3 + 0)) * HH + yy) * WW + xx] * (1.0f / 15.0f);
    float f3 = img[(((size_t)(n * 3 + 1)) * HH + yy) * WW + xx] * (1.0f / 15.0f);
    float f4 = img[(((size_t)(n * 3 + 2)) * HH + yy) * WW + xx] * (1.0f / 15.0f);
    g_feat[n][0][p] = f0; g_feat[n][1][p] = f1; g_feat[n][2][p] = f2;
    g_feat[n][3][p] = f3; g_feat[n][4][p] = f4;
    g_a0[n][p] = CNEG * (f0*f0 + f1*f1 + f2*f2 + f3*f3 + f4*f4);
}

// ---------------------------------------------------------------------------
// Phase 2: pair loop, 2 q's per iteration via fp32x2.
// smem layout: ssp[jj][2k+c] = seg_k(q0+2jj+c)  -> u64 index k is a q-pair.
//              qdi[jj][2c+e]: c=0..4 feat, 5 gate, 6 a0.
// Diagonal tiles: full ordered sum with g_p only (== triangular (g_p+g_q) sum
// plus the self term, by symmetry of w*dot).
// ---------------------------------------------------------------------------
__global__ __launch_bounds__(PT) void pair_kernel() {
    __shared__ float ssp[QT / 2][48];   // 24 KB, row = 24 u64 (21 used)
    __shared__ float qdi[QT / 2][16];   // 8 KB,  row = 8 u64 (7 used)
    __shared__ float red[PT / 32];

    int t = threadIdx.x;
    int n = blockIdx.z;

    int idx = blockIdx.x, bp = 0;
    while (idx >= NPT - bp) { idx -= NPT - bp; bp++; }
    int bq = bp + idx;
    bool diag = (bp == bq);

    int p  = bp * PT + t;
    int q0 = bq * QT;

    {
        int jj = t >> 1, c = t & 1;
        int q = q0 + t;
#pragma unroll
        for (int k = 0; k < KC; k++) ssp[jj][2 * k + c] = g_seg[n][k][q];
#pragma unroll
        for (int cc = 0; cc < 5; cc++) qdi[jj][2 * cc + c] = g_feat[n][cc][q];
        qdi[jj][10 + c] = g_gate[n][q];
        qdi[jj][12 + c] = g_a0[n][q];
    }
    __syncthreads();

    u64 fpl[5];
#pragma unroll
    for (int c = 0; c < 5; c++) {
        float f = LOG2E * g_feat[n][c][p];
        fpl[c] = pack2(f, f);
    }
    float a0p = g_a0[n][p];
    u64 a0p2 = pack2(a0p, a0p);
    float gp = g_gate[n][p];
    u64 spp[KC];
#pragma unroll
    for (int k = 0; k < KC; k++) {
        float s = g_seg[n][k][p];
        spp[k] = pack2(s, s);
    }

    u64 accA = 0, accB = 0;

#pragma unroll 2
    for (int jj = 0; jj < QT / 2; jj++) {
        const ulonglong2* qr = (const ulonglong2*)&qdi[jj][0];
        ulonglong2 q01 = qr[0];          // f0,f1 pairs
        ulonglong2 q23 = qr[1];          // f2,f3 pairs
        ulonglong2 q4g = qr[2];          // f4, gate pairs
        u64 a0q = ((const u64*)&qdi[jj][0])[6];

        u64 arg = fma2(fpl[0], q01.x, a0p2);
        arg = fma2(fpl[1], q01.y, arg);
        arg = fma2(fpl[2], q23.x, arg);
        arg = fma2(fpl[3], q23.y, arg);
        arg = fma2(fpl[4], q4g.x, arg);
        arg = add2(arg, a0q);

        float a0_, a1_;
        unpack2(arg, a0_, a1_);
        u64 wp = pack2(ex2(a0_), ex2(a1_));

        const ulonglong2* sr = (const ulonglong2*)&ssp[jj][0];
        ulonglong2 s01 = sr[0], s23 = sr[1], s45 = sr[2], s67 = sr[3], s89 = sr[4];
        ulonglong2 sAB = sr[5], sCD = sr[6], sEF = sr[7], sGH = sr[8], sIJ = sr[9];
        u64 sK = ((const u64*)&ssp[jj][0])[20];

        u64 dA = mul2(spp[0], s01.x);
        u64 dB = mul2(spp[1], s01.y);
        dA = fma2(spp[2],  s23.x, dA);  dB = fma2(spp[3],  s23.y, dB);
        dA = fma2(spp[4],  s45.x, dA);  dB = fma2(spp[5],  s45.y, dB);
        dA = fma2(spp[6],  s67.x, dA);  dB = fma2(spp[7],  s67.y, dB);
        dA = fma2(spp[8],  s89.x, dA);  dB = fma2(spp[9],  s89.y, dB);
        dA = fma2(spp[10], sAB.x, dA);  dB = fma2(spp[11], sAB.y, dB);
        dA = fma2(spp[12], sCD.x, dA);  dB = fma2(spp[13], sCD.y, dB);
        dA = fma2(spp[14], sEF.x, dA);  dB = fma2(spp[15], sEF.y, dB);
        dA = fma2(spp[16], sGH.x, dA);  dB = fma2(spp[17], sGH.y, dB);
        dA = fma2(spp[18], sIJ.x, dA);  dB = fma2(spp[19], sIJ.y, dB);
        dA = fma2(spp[20], sK,    dA);
        u64 dot = add2(dA, dB);

        u64 wd = mul2(wp, dot);
        accA = add2(accA, wd);
        accB = fma2(wd, q4g.y, accB);
    }

    float ax, ay, bx, by;
    unpack2(accA, ax, ay);
    unpack2(accB, bx, by);
    float val = gp * (ax + ay);
    if (!diag) val += bx + by;

#pragma unroll
    for (int o = 16; o > 0; o >>= 1)
        val += __shfl_down_sync(0xffffffffu, val, o);
    if ((t & 31) == 0) red[t >> 5] = val;
    __syncthreads();
    if (t == 0) {
        float s = 0.0f;
#pragma unroll
        for (int w = 0; w < PT / 32; w++) s += red[w];
        g_part[(size_t)blockIdx.z * NTRI + blockIdx.x] = s;
    }
}

// ---------------------------------------------------------------------------
__global__ void final_kernel(float* __restrict__ out) {
    __shared__ float red[8];
    int t = threadIdx.x;  // 256
    float v = 0.0f;
    for (int i = t; i < NBLK; i += 256) v += g_part[i];
#pragma unroll
    for (int o = 16; o > 0; o >>= 1)
        v += __shfl_down_sync(0xffffffffu, v, o);
    if ((t & 31) == 0) red[t >> 5] = v;
    __syncthreads();
    if (t == 0) {
        float s = 0.0f;
#pragma unroll
        for (int w = 0; w < 8; w++) s += red[w];
        out[0] = s * (-0.05f / 16384.0f);
    }
}

extern "C" void kernel_launch(void* const* d_in, const int* in_sizes, int n_in,
                              void* d_out, int out_size) {
    const float* img = (const float*)d_in[0];
    const float* seg = (const float*)d_in[1];
    const float* roi = (const float*)d_in[2];
    const float* lab = (const float*)d_in[3];
    float* out = (float*)d_out;

    prep1_kernel<<<(NB * KC * PTOT) / 256, 256>>>(seg);
    prep2_kernel<<<(NB * PTOT) / 256, 256>>>(img, roi, lab);
    dim3 grid(NTRI, 1, NB);
    pair_kernel<<<grid, PT>>>();
    final_kernel<<<1, 256>>>(out);
}

// round 5
// speedup vs baseline: 5.2793x; 2.0931x over previous
#include <cuda_runtime.h>
#include <cuda_fp16.h>
#include <stdint.h>

// DenseEnergyLoss via warp-level fp16 tensor-core GEMMs + fp32 exp epilogue.
// S = sum over ordered tile pairs (bp<=bq):
//   off-diag: (g_p+g_q) * exp(arg) * dot21 ;  diag: g_p * exp(arg) * dot21
// arg = a0v(p) + a0u(q) + v_p . u_q  ==  -(0.5/L)|L v_p - u_q|^2  (exact quadratic)
// out = -0.05 * S / 16384

#define NB   4
#define KC   21
#define HH   128
#define WW   128
#define PTOT 4096
#define TS   256
#define NPT  (PTOT/TS)          // 16
#define NTRI (NPT*(NPT+1)/2)    // 136
#define NBLK (NTRI*NB)          // 544

#define LOG2E 1.4426950408889634f
#define SPAD  264               // smem row stride (8 mod 32 -> conflict-free B frags)

__device__ uint32_t g_sp16[NB][16][PTOT];  // half2 seg k-pairs (k padded to 32)
__device__ uint32_t g_vf  [NB][4][PTOT];   // half2 v-feature pairs (p-side)
__device__ uint32_t g_uf  [NB][4][PTOT];   // half2 u-feature pairs (q-side, *LOG2E)
__device__ float    g_a0v [NB][PTOT];
__device__ float    g_a0u [NB][PTOT];
__device__ float    g_gate[NB][PTOT];
__device__ float    g_raw [NB][KC][PTOT];
__device__ float    g_part[NBLK];
__device__ int      g_cnt;                 // zero-init; last block resets to 0

__device__ __forceinline__ float ex2(float x) {
    float y; asm("ex2.approx.f32 %0, %1;" : "=f"(y) : "f"(x)); return y;
}
__device__ __forceinline__ uint32_t h2(float a, float b) {
    __half2 h = __floats2half2_rn(a, b);
    return *(uint32_t*)&h;
}
__device__ __forceinline__ void mma16816(float d[4],
    uint32_t a0, uint32_t a1, uint32_t a2, uint32_t a3,
    uint32_t b0, uint32_t b1) {
    asm volatile("mma.sync.aligned.m16n8k16.row.col.f32.f16.f16.f32 "
        "{%0,%1,%2,%3}, {%4,%5,%6,%7}, {%8,%9}, {%0,%1,%2,%3};"
        : "+f"(d[0]), "+f"(d[1]), "+f"(d[2]), "+f"(d[3])
        : "r"(a0), "r"(a1), "r"(a2), "r"(a3), "r"(b0), "r"(b1));
}

// ---------------------------------------------------------------------------
// Phase 1a: 2x2 box downsample of seg.
// ---------------------------------------------------------------------------
__global__ void prep1_kernel(const float* __restrict__ seg) {
    int idx = blockIdx.x * blockDim.x + threadIdx.x;   // NB*KC*PTOT
    int n = idx / (KC * PTOT);
    int rem = idx - n * (KC * PTOT);
    int k = rem >> 12;
    int p = rem & (PTOT - 1);
    int y = p >> 6, x = p & 63;
    const float2* r0 = (const float2*)(seg + (((size_t)(n * KC + k) * HH + 2 * y) * WW + 2 * x));
    const float2* r1 = r0 + (WW / 2);
    float2 a = r0[0], b = r1[0];
    g_raw[n][k][p] = 0.25f * (a.x + a.y + b.x + b.y);
}

// ---------------------------------------------------------------------------
// Phase 1b: gate, fp16 packing of seg & features, fp32 a0 terms.
// ---------------------------------------------------------------------------
__global__ void prep2_kernel(const float* __restrict__ img,
                             const float* __restrict__ roi,
                             const float* __restrict__ lab) {
    int idx = blockIdx.x * blockDim.x + threadIdx.x;   // NB*PTOT
    int n = idx >> 12;
    int p = idx & (PTOT - 1);
    int y = p >> 6, x = p & 63;
    int yy = 2 * y, xx = 2 * x;

    float s[KC];
    float maxs = -1e30f;
#pragma unroll
    for (int k = 0; k < KC; k++) {
        float v = g_raw[n][k][p];
        s[k] = v;
        maxs = fmaxf(maxs, v);
    }
    float r  = roi[((size_t)n * HH + yy) * WW + xx];
    float lv = lab[((size_t)n * HH + yy) * WW + xx];
    float gate = ((int)lv == 255) ? 1.0f : (r - maxs);
    g_gate[n][p] = fmaxf(gate, 0.0f);

#pragma unroll
    for (int k = 0; k < KC; k++) s[k] *= r;
#pragma unroll
    for (int kp = 0; kp < 10; kp++) g_sp16[n][kp][p] = h2(s[2*kp], s[2*kp+1]);
    g_sp16[n][10][p] = h2(s[20], 0.0f);
#pragma unroll
    for (int kp = 11; kp < 16; kp++) g_sp16[n][kp][p] = 0u;

    float f[5];
    f[0] = (float)x * (1.0f / 40.0f);
    f[1] = (float)y * (1.0f / 40.0f);
    f[2] = img[(((size_t)(n * 3 + 0)) * HH + yy) * WW + xx] * (1.0f / 15.0f);
    f[3] = img[(((size_t)(n * 3 + 1)) * HH + yy) * WW + xx] * (1.0f / 15.0f);
    f[4] = img[(((size_t)(n * 3 + 2)) * HH + yy) * WW + xx] * (1.0f / 15.0f);

    float sv = 0.0f, su = 0.0f;
    float vr[5], ur[5];
#pragma unroll
    for (int c = 0; c < 5; c++) {
        vr[c] = __half2float(__float2half(f[c]));
        ur[c] = __half2float(__float2half(LOG2E * f[c]));
        sv += vr[c] * vr[c];
        su += ur[c] * ur[c];
    }
    g_a0v[n][p] = -0.5f * LOG2E * sv;
    g_a0u[n][p] = (-0.5f / LOG2E) * su;

    g_vf[n][0][p] = h2(vr[0], vr[1]);
    g_vf[n][1][p] = h2(vr[2], vr[3]);
    g_vf[n][2][p] = h2(vr[4], 0.0f);
    g_vf[n][3][p] = 0u;
    g_uf[n][0][p] = h2(ur[0], ur[1]);
    g_uf[n][1][p] = h2(ur[2], ur[3]);
    g_uf[n][2][p] = h2(ur[4], 0.0f);
    g_uf[n][3][p] = 0u;
}

// ---------------------------------------------------------------------------
// Phase 2: tile-pair kernel. Block = 256 thr (8 warps), tile 256p x 256q.
// Warp w owns p-rows [w*32, w*32+32) as two 16-row MMA subtiles.
// q swept in chunks of 8 (one N8 MMA column).
// ---------------------------------------------------------------------------
__global__ __launch_bounds__(256) void pair_kernel(float* __restrict__ out) {
    __shared__ uint32_t sseg[16][SPAD];     // q-side seg half2, [kpair][q]
    __shared__ uint32_t sfeat[4][SPAD];     // q-side u-feature half2
    __shared__ __align__(16) float sa0g[2 * TS];  // (a0u, gate) per q
    __shared__ float red[8];
    __shared__ int isLast;

    int t = threadIdx.x;
    int n = blockIdx.z;

    int idx = blockIdx.x, bp = 0;
    while (idx >= NPT - bp) { idx -= NPT - bp; bp++; }
    int bq = bp + idx;
    float offd = (bp == bq) ? 0.0f : 1.0f;

    int p0 = bp * TS, q0 = bq * TS;

#pragma unroll
    for (int kp = 0; kp < 16; kp++) sseg[kp][t] = g_sp16[n][kp][q0 + t];
#pragma unroll
    for (int c = 0; c < 4; c++) sfeat[c][t] = g_uf[n][c][q0 + t];
    sa0g[2 * t]     = g_a0u[n][q0 + t];
    sa0g[2 * t + 1] = g_gate[n][q0 + t];
    __syncthreads();

    int w = t >> 5, lane = t & 31;
    int g = lane >> 2, four = lane & 3;
    int prb = p0 + w * 32 + g;

    // p-side fragments (loop-invariant), direct from global
    uint32_t A1[2][2], A2[2][2][4];
    float a0p[2][2], gp[2][2];
#pragma unroll
    for (int s = 0; s < 2; s++) {
        int base = prb + s * 16;
        A1[s][0] = g_vf[n][four][base];
        A1[s][1] = g_vf[n][four][base + 8];
        A2[s][0][0] = g_sp16[n][four][base];
        A2[s][0][1] = g_sp16[n][four][base + 8];
        A2[s][0][2] = g_sp16[n][four + 4][base];
        A2[s][0][3] = g_sp16[n][four + 4][base + 8];
        A2[s][1][0] = g_sp16[n][four + 8][base];
        A2[s][1][1] = g_sp16[n][four + 8][base + 8];
        A2[s][1][2] = g_sp16[n][four + 12][base];
        A2[s][1][3] = g_sp16[n][four + 12][base + 8];
        a0p[s][0] = g_a0v[n][base];
        a0p[s][1] = g_a0v[n][base + 8];
        gp[s][0]  = g_gate[n][base];
        gp[s][1]  = g_gate[n][base + 8];
    }

    float acc = 0.0f;

#pragma unroll 4
    for (int chunk = 0; chunk < TS / 8; chunk++) {
        int qc = chunk * 8;
        int qb = qc + g;
        uint32_t b1  = sfeat[four][qb];
        uint32_t b2a = sseg[four][qb];
        uint32_t b2b = sseg[four + 4][qb];
        uint32_t b2c = sseg[four + 8][qb];
        uint32_t b2d = sseg[four + 12][qb];
        int c0 = qc + 2 * four;
        float4 ag = *(const float4*)&sa0g[2 * c0];   // a0q0, g0, a0q1, g1
        float gq0 = ag.y * offd;
        float gq1 = ag.w * offd;

#pragma unroll
        for (int s = 0; s < 2; s++) {
            float d1[4] = {0.f, 0.f, 0.f, 0.f};
            mma16816(d1, A1[s][0], A1[s][1], 0u, 0u, b1, 0u);
            float d2[4] = {0.f, 0.f, 0.f, 0.f};
            mma16816(d2, A2[s][0][0], A2[s][0][1], A2[s][0][2], A2[s][0][3], b2a, b2b);
            mma16816(d2, A2[s][1][0], A2[s][1][1], A2[s][1][2], A2[s][1][3], b2c, b2d);

            float w00 = ex2(a0p[s][0] + ag.x + d1[0]);
            float w01 = ex2(a0p[s][0] + ag.z + d1[1]);
            float w10 = ex2(a0p[s][1] + ag.x + d1[2]);
            float w11 = ex2(a0p[s][1] + ag.z + d1[3]);
            acc = fmaf(w00 * d2[0], gp[s][0] + gq0, acc);
            acc = fmaf(w01 * d2[1], gp[s][0] + gq1, acc);
            acc = fmaf(w10 * d2[2], gp[s][1] + gq0, acc);
            acc = fmaf(w11 * d2[3], gp[s][1] + gq1, acc);
        }
    }

    // block reduction (deterministic)
#pragma unroll
    for (int o = 16; o > 0; o >>= 1)
        acc += __shfl_down_sync(0xffffffffu, acc, o);
    if (lane == 0) red[w] = acc;
    __syncthreads();
    if (t == 0) {
        float s = 0.0f;
#pragma unroll
        for (int i = 0; i < 8; i++) s += red[i];
        g_part[(size_t)n * NTRI + blockIdx.x] = s;
        __threadfence();
        int old = atomicAdd(&g_cnt, 1);
        isLast = (old == NBLK - 1);
    }
    __syncthreads();

    if (isLast && t < 32) {
        __threadfence();
        float v = 0.0f;
        for (int i = t; i < NBLK; i += 32) v += g_part[i];   // fixed order per lane
#pragma unroll
        for (int o = 16; o > 0; o >>= 1)
            v += __shfl_down_sync(0xffffffffu, v, o);
        if (t == 0) {
            out[0] = v * (-0.05f / 16384.0f);
            g_cnt = 0;   // reset for next graph replay
        }
    }
}

extern "C" void kernel_launch(void* const* d_in, const int* in_sizes, int n_in,
                              void* d_out, int out_size) {
    const float* img = (const float*)d_in[0];
    const float* seg = (const float*)d_in[1];
    const float* roi = (const float*)d_in[2];
    const float* lab = (const float*)d_in[3];
    float* out = (float*)d_out;

    prep1_kernel<<<(NB * KC * PTOT) / 256, 256>>>(seg);
    prep2_kernel<<<(NB * PTOT) / 256, 256>>>(img, roi, lab);
    dim3 grid(NTRI, 1, NB);
    pair_kernel<<<grid, 256>>>(out);
}

// round 6
// speedup vs baseline: 5.6377x; 1.0679x over previous
#include <cuda_runtime.h>
#include <cuda_fp16.h>
#include <stdint.h>

// DenseEnergyLoss: fp16 tensor-core GEMMs + fp32 exp epilogue, fused prep.
// arg = a0v(p)+a0u(q)+v_p.u_q == -(0.5/L)|L v_p - u_q|^2  (exact quadratic, w<=1)
// out = -0.05 * S / 16384

#define NB   4
#define KC   21
#define HH   128
#define WW   128
#define PTOT 4096
#define TS   256
#define NPT  (PTOT/TS)          // 16
#define NTRI (NPT*(NPT+1)/2)    // 136
#define NBLK (NTRI*NB)          // 544
#define KP   11                 // used k-pairs (21 halves)

#define LOG2E 1.4426950408889634f
#define SPAD  264               // smem row stride words (8 mod 32 -> conflict-free)

// rows 11 of g_sp16 and row 3 of g_vf/g_uf are never written -> stay zero.
__device__ uint32_t g_sp16[NB][12][PTOT];  // half2 seg*roi k-pairs
__device__ uint32_t g_vf  [NB][4][PTOT];   // half2 v-feature pairs (p-side)
__device__ uint32_t g_uf  [NB][4][PTOT];   // half2 u-feature pairs (q-side, *LOG2E)
__device__ float    g_a0v [NB][PTOT];
__device__ float    g_a0u [NB][PTOT];
__device__ float    g_gate[NB][PTOT];
__device__ float    g_part[NBLK];
__device__ int      g_cnt;                 // zero-init; last block resets

__device__ __forceinline__ float ex2(float x) {
    float y; asm("ex2.approx.f32 %0, %1;" : "=f"(y) : "f"(x)); return y;
}
__device__ __forceinline__ uint32_t h2(float a, float b) {
    __half2 h = __floats2half2_rn(a, b);
    return *(uint32_t*)&h;
}
__device__ __forceinline__ void mma_k16(float d[4],
    uint32_t a0, uint32_t a1, uint32_t a2, uint32_t a3,
    uint32_t b0, uint32_t b1) {
    asm volatile("mma.sync.aligned.m16n8k16.row.col.f32.f16.f16.f32 "
        "{%0,%1,%2,%3}, {%4,%5,%6,%7}, {%8,%9}, {%0,%1,%2,%3};"
        : "+f"(d[0]), "+f"(d[1]), "+f"(d[2]), "+f"(d[3])
        : "r"(a0), "r"(a1), "r"(a2), "r"(a3), "r"(b0), "r"(b1));
}
__device__ __forceinline__ void mma_k8(float d[4],
    uint32_t a0, uint32_t a1, uint32_t b0) {
    asm volatile("mma.sync.aligned.m16n8k8.row.col.f32.f16.f16.f32 "
        "{%0,%1,%2,%3}, {%4,%5}, {%6}, {%0,%1,%2,%3};"
        : "+f"(d[0]), "+f"(d[1]), "+f"(d[2]), "+f"(d[3])
        : "r"(a0), "r"(a1), "r"(b0));
}

// ---------------------------------------------------------------------------
// Phase 1a: fused downsample + roi multiply + fp16 k-pair pack.
// Thread handles (n, kp, 4 consecutive p along x). 8x LDG.128 -> 1x STG.128.
// ---------------------------------------------------------------------------
__global__ void prep1_kernel(const float* __restrict__ seg,
                             const float* __restrict__ roi) {
    int idx = blockIdx.x * blockDim.x + threadIdx.x;   // NB*KP*1024
    int n = idx / (KP * 1024);
    int rem = idx - n * (KP * 1024);
    int kp = rem >> 10;
    int pq = rem & 1023;
    int p = pq << 2;                // 4 consecutive p (same y)
    int y = p >> 6, x = p & 63;
    int k0 = 2 * kp;

    const float4* s0 = (const float4*)(seg + (((size_t)(n * KC + k0) * HH + 2 * y) * WW + 2 * x));
    float4 a0 = s0[0], a1 = s0[1];
    float4 b0 = s0[WW / 4], b1 = s0[WW / 4 + 1];

    const float4* rr = (const float4*)(roi + ((size_t)n * HH + 2 * y) * WW + 2 * x);
    float4 r0 = rr[0], r1 = rr[1];
    float rv[4] = {r0.x, r0.z, r1.x, r1.z};

    float sA[4];
    sA[0] = 0.25f * (a0.x + a0.y + b0.x + b0.y);
    sA[1] = 0.25f * (a0.z + a0.w + b0.z + b0.w);
    sA[2] = 0.25f * (a1.x + a1.y + b1.x + b1.y);
    sA[3] = 0.25f * (a1.z + a1.w + b1.z + b1.w);

    float sB[4] = {0.f, 0.f, 0.f, 0.f};
    if (kp < 10) {   // k1 = 2kp+1 < 21
        const float4* s1 = (const float4*)(seg + (((size_t)(n * KC + k0 + 1) * HH + 2 * y) * WW + 2 * x));
        float4 c0 = s1[0], c1 = s1[1];
        float4 d0 = s1[WW / 4], d1 = s1[WW / 4 + 1];
        sB[0] = 0.25f * (c0.x + c0.y + d0.x + d0.y);
        sB[1] = 0.25f * (c0.z + c0.w + d0.z + d0.w);
        sB[2] = 0.25f * (c1.x + c1.y + d1.x + d1.y);
        sB[3] = 0.25f * (c1.z + c1.w + d1.z + d1.w);
    }

    uint4 outw;
    outw.x = h2(sA[0] * rv[0], sB[0] * rv[0]);
    outw.y = h2(sA[1] * rv[1], sB[1] * rv[1]);
    outw.z = h2(sA[2] * rv[2], sB[2] * rv[2]);
    outw.w = h2(sA[3] * rv[3], sB[3] * rv[3]);
    *(uint4*)&g_sp16[n][kp][p] = outw;
}

// ---------------------------------------------------------------------------
// Phase 1b: gate (max recovered from packed fp16 / roi), features, a0 terms.
// ---------------------------------------------------------------------------
__global__ void prep2_kernel(const float* __restrict__ img,
                             const float* __restrict__ roi,
                             const float* __restrict__ lab) {
    int idx = blockIdx.x * blockDim.x + threadIdx.x;   // NB*PTOT
    int n = idx >> 12;
    int p = idx & (PTOT - 1);
    int y = p >> 6, x = p & 63;
    int yy = 2 * y, xx = 2 * x;

    __half2 hmax = __floats2half2_rn(0.0f, 0.0f);
#pragma unroll
    for (int kp = 0; kp < KP; kp++) {
        uint32_t m = g_sp16[n][kp][p];
        hmax = __hmax2(hmax, *(__half2*)&m);
    }
    float mx = fmaxf(__low2float(hmax), __high2float(hmax));

    float r  = roi[((size_t)n * HH + yy) * WW + xx];
    float lv = lab[((size_t)n * HH + yy) * WW + xx];
    float inv = (r > 0.0f) ? __frcp_rn(r) : 0.0f;
    float gate = ((int)lv == 255) ? 1.0f : (r - mx * inv);
    g_gate[n][p] = fmaxf(gate, 0.0f);

    float f[5];
    f[0] = (float)x * (1.0f / 40.0f);
    f[1] = (float)y * (1.0f / 40.0f);
    f[2] = img[(((size_t)(n * 3 + 0)) * HH + yy) * WW + xx] * (1.0f / 15.0f);
    f[3] = img[(((size_t)(n * 3 + 1)) * HH + yy) * WW + xx] * (1.0f / 15.0f);
    f[4] = img[(((size_t)(n * 3 + 2)) * HH + yy) * WW + xx] * (1.0f / 15.0f);

    float sv = 0.0f, su = 0.0f, vr[5], ur[5];
#pragma unroll
    for (int c = 0; c < 5; c++) {
        vr[c] = __half2float(__float2half(f[c]));
        ur[c] = __half2float(__float2half(LOG2E * f[c]));
        sv += vr[c] * vr[c];
        su += ur[c] * ur[c];
    }
    g_a0v[n][p] = -0.5f * LOG2E * sv;
    g_a0u[n][p] = (-0.5f / LOG2E) * su;

    g_vf[n][0][p] = h2(vr[0], vr[1]);
    g_vf[n][1][p] = h2(vr[2], vr[3]);
    g_vf[n][2][p] = h2(vr[4], 0.0f);
    g_uf[n][0][p] = h2(ur[0], ur[1]);
    g_uf[n][1][p] = h2(ur[2], ur[3]);
    g_uf[n][2][p] = h2(ur[4], 0.0f);
}

// ---------------------------------------------------------------------------
// Phase 2: tile-pair kernel. 256 thr, 256p x 256q. Per warp-chunk (32p x 8q):
// dot5 = 1x mma.k8 ; dot21 = 1x mma.k16 + 1x mma.k8.
// ---------------------------------------------------------------------------
__global__ __launch_bounds__(256) void pair_kernel(float* __restrict__ out) {
    __shared__ uint32_t sseg[12][SPAD];
    __shared__ uint32_t sfeat[4][SPAD];
    __shared__ __align__(16) float sa0g[2 * TS];
    __shared__ float red[8];
    __shared__ int isLast;

    int t = threadIdx.x;
    int n = blockIdx.z;

    int idx = blockIdx.x, bp = 0;
    while (idx >= NPT - bp) { idx -= NPT - bp; bp++; }
    int bq = bp + idx;
    float offd = (bp == bq) ? 0.0f : 1.0f;

    int p0 = bp * TS, q0 = bq * TS;

#pragma unroll
    for (int kp = 0; kp < KP; kp++) sseg[kp][t] = g_sp16[n][kp][q0 + t];
    sseg[11][t] = 0u;
#pragma unroll
    for (int c = 0; c < 4; c++) sfeat[c][t] = g_uf[n][c][q0 + t];
    sa0g[2 * t]     = g_a0u[n][q0 + t];
    sa0g[2 * t + 1] = g_gate[n][q0 + t];
    __syncthreads();

    int w = t >> 5, lane = t & 31;
    int g = lane >> 2, four = lane & 3;
    int prb = p0 + w * 32 + g;

    uint32_t A1[2][2], A2[2][4], A3[2][2];
    float a0p[2][2], gp[2][2];
#pragma unroll
    for (int s = 0; s < 2; s++) {
        int base = prb + s * 16;
        A1[s][0] = g_vf[n][four][base];
        A1[s][1] = g_vf[n][four][base + 8];
        A2[s][0] = g_sp16[n][four][base];
        A2[s][1] = g_sp16[n][four][base + 8];
        A2[s][2] = g_sp16[n][four + 4][base];
        A2[s][3] = g_sp16[n][four + 4][base + 8];
        A3[s][0] = g_sp16[n][8 + four][base];
        A3[s][1] = g_sp16[n][8 + four][base + 8];
        a0p[s][0] = g_a0v[n][base];
        a0p[s][1] = g_a0v[n][base + 8];
        gp[s][0]  = g_gate[n][base];
        gp[s][1]  = g_gate[n][base + 8];
    }

    float acc = 0.0f;

#pragma unroll 4
    for (int chunk = 0; chunk < TS / 8; chunk++) {
        int qc = chunk * 8;
        int qb = qc + g;
        uint32_t b1  = sfeat[four][qb];
        uint32_t b2a = sseg[four][qb];
        uint32_t b2b = sseg[four + 4][qb];
        uint32_t b2c = sseg[8 + four][qb];
        int c0 = qc + 2 * four;
        float4 ag = *(const float4*)&sa0g[2 * c0];   // a0q0, g0, a0q1, g1
        float gq0 = ag.y * offd;
        float gq1 = ag.w * offd;

#pragma unroll
        for (int s = 0; s < 2; s++) {
            float d1[4] = {0.f, 0.f, 0.f, 0.f};
            mma_k8(d1, A1[s][0], A1[s][1], b1);
            float d2[4] = {0.f, 0.f, 0.f, 0.f};
            mma_k16(d2, A2[s][0], A2[s][1], A2[s][2], A2[s][3], b2a, b2b);
            mma_k8(d2, A3[s][0], A3[s][1], b2c);

            float w00 = ex2(a0p[s][0] + ag.x + d1[0]);
            float w01 = ex2(a0p[s][0] + ag.z + d1[1]);
            float w10 = ex2(a0p[s][1] + ag.x + d1[2]);
            float w11 = ex2(a0p[s][1] + ag.z + d1[3]);
            acc = fmaf(w00 * d2[0], gp[s][0] + gq0, acc);
            acc = fmaf(w01 * d2[1], gp[s][0] + gq1, acc);
            acc = fmaf(w10 * d2[2], gp[s][1] + gq0, acc);
            acc = fmaf(w11 * d2[3], gp[s][1] + gq1, acc);
        }
    }

#pragma unroll
    for (int o = 16; o > 0; o >>= 1)
        acc += __shfl_down_sync(0xffffffffu, acc, o);
    if (lane == 0) red[w] = acc;
    __syncthreads();
    if (t == 0) {
        float s = 0.0f;
#pragma unroll
        for (int i = 0; i < 8; i++) s += red[i];
        g_part[(size_t)n * NTRI + blockIdx.x] = s;
        __threadfence();
        int old = atomicAdd(&g_cnt, 1);
        isLast = (old == NBLK - 1);
    }
    __syncthreads();

    if (isLast && t < 32) {
        __threadfence();
        float v = 0.0f;
        for (int i = t; i < NBLK; i += 32) v += g_part[i];
#pragma unroll
        for (int o = 16; o > 0; o >>= 1)
            v += __shfl_down_sync(0xffffffffu, v, o);
        if (t == 0) {
            out[0] = v * (-0.05f / 16384.0f);
            g_cnt = 0;
        }
    }
}

extern "C" void kernel_launch(void* const* d_in, const int* in_sizes, int n_in,
                              void* d_out, int out_size) {
    const float* img = (const float*)d_in[0];
    const float* seg = (const float*)d_in[1];
    const float* roi = (const float*)d_in[2];
    const float* lab = (const float*)d_in[3];
    float* out = (float*)d_out;

    prep1_kernel<<<(NB * KP * 1024) / 256, 256>>>(seg, roi);
    prep2_kernel<<<(NB * PTOT) / 128, 128>>>(img, roi, lab);
    dim3 grid(NTRI, 1, NB);
    pair_kernel<<<grid, 256>>>(out);
}

// round 10
// speedup vs baseline: 5.7086x; 1.0126x over previous
#include <cuda_runtime.h>
#include <cuda_fp16.h>
#include <stdint.h>

// DenseEnergyLoss: fp16 tensor-core GEMMs + fp32 exp epilogue, fused prep.
// arg = a0v(p)+a0u(q)+v_p.u_q == -(0.5/L)|L v_p - u_q|^2  (exact quadratic, w<=1)
// out = -0.05 * S / 16384

#define NB   4
#define KC   21
#define HH   128
#define WW   128
#define PTOT 4096
#define TS   256
#define NPT  (PTOT/TS)          // 16
#define NTRI (NPT*(NPT+1)/2)    // 136
#define NBLK (NTRI*NB)          // 544
#define KP   11                 // used k-pairs (21 halves)

#define LOG2E 1.4426950408889634f
#define SPAD  264               // smem row stride words (8 mod 32 -> conflict-free)

__device__ uint32_t g_sp16[NB][12][PTOT];  // half2 seg*roi k-pairs (row 11 stays 0)
__device__ uint32_t g_vf  [NB][4][PTOT];   // half2 v-feature pairs (p-side)
__device__ uint32_t g_uf  [NB][4][PTOT];   // half2 u-feature pairs (q-side, *LOG2E)
__device__ float    g_a0v [NB][PTOT];
__device__ float    g_a0u [NB][PTOT];
__device__ float    g_gate[NB][PTOT];
__device__ float    g_part[NBLK];
__device__ int      g_cnt;                 // zero-init; last block resets

__device__ __forceinline__ float ex2(float x) {
    float y; asm("ex2.approx.f32 %0, %1;" : "=f"(y) : "f"(x)); return y;
}
__device__ __forceinline__ uint32_t h2(float a, float b) {
    __half2 h = __floats2half2_rn(a, b);
    return *(uint32_t*)&h;
}
__device__ __forceinline__ void mma_k16(float d[4],
    uint32_t a0, uint32_t a1, uint32_t a2, uint32_t a3,
    uint32_t b0, uint32_t b1) {
    asm volatile("mma.sync.aligned.m16n8k16.row.col.f32.f16.f16.f32 "
        "{%0,%1,%2,%3}, {%4,%5,%6,%7}, {%8,%9}, {%0,%1,%2,%3};"
        : "+f"(d[0]), "+f"(d[1]), "+f"(d[2]), "+f"(d[3])
        : "r"(a0), "r"(a1), "r"(a2), "r"(a3), "r"(b0), "r"(b1));
}
__device__ __forceinline__ void mma_k8(float d[4],
    uint32_t a0, uint32_t a1, uint32_t b0) {
    asm volatile("mma.sync.aligned.m16n8k8.row.col.f32.f16.f16.f32 "
        "{%0,%1,%2,%3}, {%4,%5}, {%6}, {%0,%1,%2,%3};"
        : "+f"(d[0]), "+f"(d[1]), "+f"(d[2]), "+f"(d[3])
        : "r"(a0), "r"(a1), "r"(b0));
}

// ---------------------------------------------------------------------------
// Phase 1a: fused downsample + roi multiply + fp16 k-pair pack.
// Thread handles (n, kp, 2 consecutive p). Finer grain -> 352 blocks for MLP.
// ---------------------------------------------------------------------------
__global__ void prep1_kernel(const float* __restrict__ seg,
                             const float* __restrict__ roi) {
    int idx = blockIdx.x * blockDim.x + threadIdx.x;   // NB*KP*2048
    int n = idx / (KP * 2048);
    int rem = idx - n * (KP * 2048);
    int kp = rem >> 11;
    int pq = rem & 2047;
    int p = pq << 1;                // 2 consecutive p (same y)
    int y = p >> 6, x = p & 63;
    int k0 = 2 * kp;

    const float4* s0 = (const float4*)(seg + (((size_t)(n * KC + k0) * HH + 2 * y) * WW + 2 * x));
    float4 a0 = s0[0];
    float4 b0 = s0[WW / 4];

    const float4* rr = (const float4*)(roi + ((size_t)n * HH + 2 * y) * WW + 2 * x);
    float4 r0 = rr[0];
    float rv0 = r0.x, rv1 = r0.z;

    float sA0 = 0.25f * (a0.x + a0.y + b0.x + b0.y);
    float sA1 = 0.25f * (a0.z + a0.w + b0.z + b0.w);

    float sB0 = 0.0f, sB1 = 0.0f;
    if (kp < 10) {
        const float4* s1 = (const float4*)(seg + (((size_t)(n * KC + k0 + 1) * HH + 2 * y) * WW + 2 * x));
        float4 c0 = s1[0];
        float4 d0 = s1[WW / 4];
        sB0 = 0.25f * (c0.x + c0.y + d0.x + d0.y);
        sB1 = 0.25f * (c0.z + c0.w + d0.z + d0.w);
    }

    uint2 outw;
    outw.x = h2(sA0 * rv0, sB0 * rv0);
    outw.y = h2(sA1 * rv1, sB1 * rv1);
    *(uint2*)&g_sp16[n][kp][p] = outw;
}

// ---------------------------------------------------------------------------
// Phase 1b: gate (max recovered from packed fp16 / roi), features, a0 terms.
// ---------------------------------------------------------------------------
__global__ void prep2_kernel(const float* __restrict__ img,
                             const float* __restrict__ roi,
                             const float* __restrict__ lab) {
    int idx = blockIdx.x * blockDim.x + threadIdx.x;   // NB*PTOT
    int n = idx >> 12;
    int p = idx & (PTOT - 1);
    int y = p >> 6, x = p & 63;
    int yy = 2 * y, xx = 2 * x;

    __half2 hmax = __floats2half2_rn(0.0f, 0.0f);
#pragma unroll
    for (int kp = 0; kp < KP; kp++) {
        uint32_t m = g_sp16[n][kp][p];
        hmax = __hmax2(hmax, *(__half2*)&m);
    }
    float mx = fmaxf(__low2float(hmax), __high2float(hmax));

    float r  = roi[((size_t)n * HH + yy) * WW + xx];
    float lv = lab[((size_t)n * HH + yy) * WW + xx];
    float inv = (r > 0.0f) ? __frcp_rn(r) : 0.0f;
    float gate = ((int)lv == 255) ? 1.0f : (r - mx * inv);
    g_gate[n][p] = fmaxf(gate, 0.0f);

    float f[5];
    f[0] = (float)x * (1.0f / 40.0f);
    f[1] = (float)y * (1.0f / 40.0f);
    f[2] = img[(((size_t)(n * 3 + 0)) * HH + yy) * WW + xx] * (1.0f / 15.0f);
    f[3] = img[(((size_t)(n * 3 + 1)) * HH + yy) * WW + xx] * (1.0f / 15.0f);
    f[4] = img[(((size_t)(n * 3 + 2)) * HH + yy) * WW + xx] * (1.0f / 15.0f);

    float sv = 0.0f, su = 0.0f, vr[5], ur[5];
#pragma unroll
    for (int c = 0; c < 5; c++) {
        vr[c] = __half2float(__float2half(f[c]));
        ur[c] = __half2float(__float2half(LOG2E * f[c]));
        sv += vr[c] * vr[c];
        su += ur[c] * ur[c];
    }
    g_a0v[n][p] = -0.5f * LOG2E * sv;
    g_a0u[n][p] = (-0.5f / LOG2E) * su;

    g_vf[n][0][p] = h2(vr[0], vr[1]);
    g_vf[n][1][p] = h2(vr[2], vr[3]);
    g_vf[n][2][p] = h2(vr[4], 0.0f);
    g_uf[n][0][p] = h2(ur[0], ur[1]);
    g_uf[n][1][p] = h2(ur[2], ur[3]);
    g_uf[n][2][p] = h2(ur[4], 0.0f);
}

// ---------------------------------------------------------------------------
// Phase 2: tile-pair kernel. 256 thr (8 warps), 3 blocks/SM. 256p x 256q.
// dot5 accumulator is pre-seeded with a0p+a0q so w = ex2(d1[i]) directly.
// ---------------------------------------------------------------------------
__global__ __launch_bounds__(256, 3) void pair_kernel(float* __restrict__ out) {
    __shared__ uint32_t sseg[12][SPAD];
    __shared__ uint32_t sfeat[4][SPAD];
    __shared__ __align__(16) float sa0g[2 * TS];
    __shared__ float red[8];
    __shared__ int isLast;

    int t = threadIdx.x;
    int n = blockIdx.z;

    int idx = blockIdx.x, bp = 0;
    while (idx >= NPT - bp) { idx -= NPT - bp; bp++; }
    int bq = bp + idx;
    float offd = (bp == bq) ? 0.0f : 1.0f;

    int p0 = bp * TS, q0 = bq * TS;

#pragma unroll
    for (int kp = 0; kp < KP; kp++) sseg[kp][t] = g_sp16[n][kp][q0 + t];
    sseg[11][t] = 0u;
#pragma unroll
    for (int c = 0; c < 4; c++) sfeat[c][t] = g_uf[n][c][q0 + t];
    sa0g[2 * t]     = g_a0u[n][q0 + t];
    sa0g[2 * t + 1] = g_gate[n][q0 + t] * offd;   // pre-masked q-gate
    __syncthreads();

    int w = t >> 5, lane = t & 31;
    int g = lane >> 2, four = lane & 3;
    int prb = p0 + w * 32 + g;

    uint32_t A1[2][2], A2[2][4], A3[2][2];
    float a0p[2][2], gp[2][2];
#pragma unroll
    for (int s = 0; s < 2; s++) {
        int base = prb + s * 16;
        A1[s][0] = g_vf[n][four][base];
        A1[s][1] = g_vf[n][four][base + 8];
        A2[s][0] = g_sp16[n][four][base];
        A2[s][1] = g_sp16[n][four][base + 8];
        A2[s][2] = g_sp16[n][four + 4][base];
        A2[s][3] = g_sp16[n][four + 4][base + 8];
        A3[s][0] = g_sp16[n][8 + four][base];
        A3[s][1] = g_sp16[n][8 + four][base + 8];
        a0p[s][0] = g_a0v[n][base];
        a0p[s][1] = g_a0v[n][base + 8];
        gp[s][0]  = g_gate[n][base];
        gp[s][1]  = g_gate[n][base + 8];
    }

    float acc = 0.0f;

#pragma unroll 4
    for (int chunk = 0; chunk < TS / 8; chunk++) {
        int qc = chunk * 8;
        int qb = qc + g;
        uint32_t b1  = sfeat[four][qb];
        uint32_t b2a = sseg[four][qb];
        uint32_t b2b = sseg[four + 4][qb];
        uint32_t b2c = sseg[8 + four][qb];
        int c0 = qc + 2 * four;
        float4 ag = *(const float4*)&sa0g[2 * c0];   // a0q0, gq0', a0q1, gq1'

#pragma unroll
        for (int s = 0; s < 2; s++) {
            float d1[4];
            d1[0] = a0p[s][0] + ag.x;
            d1[1] = a0p[s][0] + ag.z;
            d1[2] = a0p[s][1] + ag.x;
            d1[3] = a0p[s][1] + ag.z;
            mma_k8(d1, A1[s][0], A1[s][1], b1);

            float d2[4] = {0.f, 0.f, 0.f, 0.f};
            mma_k16(d2, A2[s][0], A2[s][1], A2[s][2], A2[s][3], b2a, b2b);
            mma_k8(d2, A3[s][0], A3[s][1], b2c);

            float w00 = ex2(d1[0]);
            float w01 = ex2(d1[1]);
            float w10 = ex2(d1[2]);
            float w11 = ex2(d1[3]);
            acc = fmaf(w00 * d2[0], gp[s][0] + ag.y, acc);
            acc = fmaf(w01 * d2[1], gp[s][0] + ag.w, acc);
            acc = fmaf(w10 * d2[2], gp[s][1] + ag.y, acc);
            acc = fmaf(w11 * d2[3], gp[s][1] + ag.w, acc);
        }
    }

#pragma unroll
    for (int o = 16; o > 0; o >>= 1)
        acc += __shfl_down_sync(0xffffffffu, acc, o);
    if (lane == 0) red[w] = acc;
    __syncthreads();
    if (t == 0) {
        float s = 0.0f;
#pragma unroll
        for (int i = 0; i < 8; i++) s += red[i];
        g_part[(size_t)n * NTRI + blockIdx.x] = s;
        __threadfence();
        int old = atomicAdd(&g_cnt, 1);
        isLast = (old == NBLK - 1);
    }
    __syncthreads();

    if (isLast && t < 32) {
        __threadfence();
        float v = 0.0f;
        for (int i = t; i < NBLK; i += 32) v += g_part[i];
#pragma unroll
        for (int o = 16; o > 0; o >>= 1)
            v += __shfl_down_sync(0xffffffffu, v, o);
        if (t == 0) {
            out[0] = v * (-0.05f / 16384.0f);
            g_cnt = 0;
        }
    }
}

extern "C" void kernel_launch(void* const* d_in, const int* in_sizes, int n_in,
                              void* d_out, int out_size) {
    const float* img = (const float*)d_in[0];
    const float* seg = (const float*)d_in[1];
    const float* roi = (const float*)d_in[2];
    const float* lab = (const float*)d_in[3];
    float* out = (float*)d_out;

    prep1_kernel<<<(NB * KP * 2048) / 256, 256>>>(seg, roi);
    prep2_kernel<<<(NB * PTOT) / 128, 128>>>(img, roi, lab);
    dim3 grid(NTRI, 1, NB);
    pair_kernel<<<grid, 256>>>(out);
}

// round 12
// speedup vs baseline: 5.8560x; 1.0258x over previous
#include <cuda_runtime.h>
#include <cuda_fp16.h>
#include <stdint.h>

// DenseEnergyLoss: fp16 tensor-core GEMMs + fp32 exp epilogue, fused prep.
// arg = a0v(p)+a0u(q)+v_p.u_q == -(0.5/L)|L v_p - u_q|^2  (exact quadratic, w<=1)
// out = -0.05 * S / 16384

#define NB   4
#define KC   21
#define HH   128
#define WW   128
#define PTOT 4096
#define TS   256
#define NPT  (PTOT/TS)          // 16
#define NTRI (NPT*(NPT+1)/2)    // 136
#define NBLK (NTRI*NB)          // 544
#define KP   11                 // used k-pairs (21 halves)

#define LOG2E 1.4426950408889634f
#define SPAD  264               // smem row stride words (8 mod 32 -> conflict-free)

__device__ uint32_t g_sp16[NB][12][PTOT];  // half2 seg*roi k-pairs (row 11 stays 0)
__device__ uint32_t g_vf  [NB][4][PTOT];   // half2 v-feature pairs (p-side)
__device__ uint32_t g_uf  [NB][4][PTOT];   // half2 u-feature pairs (q-side, *LOG2E)
__device__ float    g_a0v [NB][PTOT];
__device__ float    g_a0u [NB][PTOT];
__device__ float    g_gate[NB][PTOT];
__device__ float    g_part[NBLK];
__device__ int      g_cnt;                 // zero-init; last block resets

__device__ __forceinline__ float ex2(float x) {
    float y; asm("ex2.approx.f32 %0, %1;" : "=f"(y) : "f"(x)); return y;
}
__device__ __forceinline__ uint32_t h2(float a, float b) {
    __half2 h = __floats2half2_rn(a, b);
    return *(uint32_t*)&h;
}
__device__ __forceinline__ void mma_k16(float d[4],
    uint32_t a0, uint32_t a1, uint32_t a2, uint32_t a3,
    uint32_t b0, uint32_t b1) {
    asm volatile("mma.sync.aligned.m16n8k16.row.col.f32.f16.f16.f32 "
        "{%0,%1,%2,%3}, {%4,%5,%6,%7}, {%8,%9}, {%0,%1,%2,%3};"
        : "+f"(d[0]), "+f"(d[1]), "+f"(d[2]), "+f"(d[3])
        : "r"(a0), "r"(a1), "r"(a2), "r"(a3), "r"(b0), "r"(b1));
}
__device__ __forceinline__ void mma_k8(float d[4],
    uint32_t a0, uint32_t a1, uint32_t b0) {
    asm volatile("mma.sync.aligned.m16n8k8.row.col.f32.f16.f16.f32 "
        "{%0,%1,%2,%3}, {%4,%5}, {%6}, {%0,%1,%2,%3};"
        : "+f"(d[0]), "+f"(d[1]), "+f"(d[2]), "+f"(d[3])
        : "r"(a0), "r"(a1), "r"(b0));
}

// ---------------------------------------------------------------------------
// Phase 1a: fused downsample + roi multiply + fp16 k-pair pack.
// ---------------------------------------------------------------------------
__global__ void prep1_kernel(const float* __restrict__ seg,
                             const float* __restrict__ roi) {
    int idx = blockIdx.x * blockDim.x + threadIdx.x;   // NB*KP*2048
    int n = idx / (KP * 2048);
    int rem = idx - n * (KP * 2048);
    int kp = rem >> 11;
    int pq = rem & 2047;
    int p = pq << 1;                // 2 consecutive p (same y)
    int y = p >> 6, x = p & 63;
    int k0 = 2 * kp;

    const float4* s0 = (const float4*)(seg + (((size_t)(n * KC + k0) * HH + 2 * y) * WW + 2 * x));
    float4 a0 = s0[0];
    float4 b0 = s0[WW / 4];

    const float4* rr = (const float4*)(roi + ((size_t)n * HH + 2 * y) * WW + 2 * x);
    float4 r0 = rr[0];
    float rv0 = r0.x, rv1 = r0.z;

    float sA0 = 0.25f * (a0.x + a0.y + b0.x + b0.y);
    float sA1 = 0.25f * (a0.z + a0.w + b0.z + b0.w);

    float sB0 = 0.0f, sB1 = 0.0f;
    if (kp < 10) {
        const float4* s1 = (const float4*)(seg + (((size_t)(n * KC + k0 + 1) * HH + 2 * y) * WW + 2 * x));
        float4 c0 = s1[0];
        float4 d0 = s1[WW / 4];
        sB0 = 0.25f * (c0.x + c0.y + d0.x + d0.y);
        sB1 = 0.25f * (c0.z + c0.w + d0.z + d0.w);
    }

    uint2 outw;
    outw.x = h2(sA0 * rv0, sB0 * rv0);
    outw.y = h2(sA1 * rv1, sB1 * rv1);
    *(uint2*)&g_sp16[n][kp][p] = outw;
}

// ---------------------------------------------------------------------------
// Phase 1b: gate (max recovered from packed fp16 / roi), features, a0 terms.
// ---------------------------------------------------------------------------
__global__ void prep2_kernel(const float* __restrict__ img,
                             const float* __restrict__ roi,
                             const float* __restrict__ lab) {
    int idx = blockIdx.x * blockDim.x + threadIdx.x;   // NB*PTOT
    int n = idx >> 12;
    int p = idx & (PTOT - 1);
    int y = p >> 6, x = p & 63;
    int yy = 2 * y, xx = 2 * x;

    __half2 hmax = __floats2half2_rn(0.0f, 0.0f);
#pragma unroll
    for (int kp = 0; kp < KP; kp++) {
        uint32_t m = g_sp16[n][kp][p];
        hmax = __hmax2(hmax, *(__half2*)&m);
    }
    float mx = fmaxf(__low2float(hmax), __high2float(hmax));

    float r  = roi[((size_t)n * HH + yy) * WW + xx];
    float lv = lab[((size_t)n * HH + yy) * WW + xx];
    float inv = (r > 0.0f) ? __frcp_rn(r) : 0.0f;
    float gate = ((int)lv == 255) ? 1.0f : (r - mx * inv);
    g_gate[n][p] = fmaxf(gate, 0.0f);

    float f[5];
    f[0] = (float)x * (1.0f / 40.0f);
    f[1] = (float)y * (1.0f / 40.0f);
    f[2] = img[(((size_t)(n * 3 + 0)) * HH + yy) * WW + xx] * (1.0f / 15.0f);
    f[3] = img[(((size_t)(n * 3 + 1)) * HH + yy) * WW + xx] * (1.0f / 15.0f);
    f[4] = img[(((size_t)(n * 3 + 2)) * HH + yy) * WW + xx] * (1.0f / 15.0f);

    float sv = 0.0f, su = 0.0f, vr[5], ur[5];
#pragma unroll
    for (int c = 0; c < 5; c++) {
        vr[c] = __half2float(__float2half(f[c]));
        ur[c] = __half2float(__float2half(LOG2E * f[c]));
        sv += vr[c] * vr[c];
        su += ur[c] * ur[c];
    }
    g_a0v[n][p] = -0.5f * LOG2E * sv;
    g_a0u[n][p] = (-0.5f / LOG2E) * su;

    g_vf[n][0][p] = h2(vr[0], vr[1]);
    g_vf[n][1][p] = h2(vr[2], vr[3]);
    g_vf[n][2][p] = h2(vr[4], 0.0f);
    g_uf[n][0][p] = h2(ur[0], ur[1]);
    g_uf[n][1][p] = h2(ur[2], ur[3]);
    g_uf[n][2][p] = h2(ur[4], 0.0f);
}

// ---------------------------------------------------------------------------
// Phase 2: tile-pair kernel. 256 thr (8 warps), 3 blocks/SM. 256p x 256q.
// 4 independent accumulators (s, d-row) -> dependent FMA chain per chunk
// shrinks from 8 to 2.
// ---------------------------------------------------------------------------
__global__ __launch_bounds__(256, 3) void pair_kernel(float* __restrict__ out) {
    __shared__ uint32_t sseg[12][SPAD];
    __shared__ uint32_t sfeat[4][SPAD];
    __shared__ __align__(16) float sa0g[2 * TS];
    __shared__ float red[8];
    __shared__ int isLast;

    int t = threadIdx.x;
    int n = blockIdx.z;

    int idx = blockIdx.x, bp = 0;
    while (idx >= NPT - bp) { idx -= NPT - bp; bp++; }
    int bq = bp + idx;
    float offd = (bp == bq) ? 0.0f : 1.0f;

    int p0 = bp * TS, q0 = bq * TS;

#pragma unroll
    for (int kp = 0; kp < KP; kp++) sseg[kp][t] = g_sp16[n][kp][q0 + t];
    sseg[11][t] = 0u;
#pragma unroll
    for (int c = 0; c < 4; c++) sfeat[c][t] = g_uf[n][c][q0 + t];
    sa0g[2 * t]     = g_a0u[n][q0 + t];
    sa0g[2 * t + 1] = g_gate[n][q0 + t] * offd;   // pre-masked q-gate
    __syncthreads();

    int w = t >> 5, lane = t & 31;
    int g = lane >> 2, four = lane & 3;
    int prb = p0 + w * 32 + g;

    uint32_t A1[2][2], A2[2][4], A3[2][2];
    float a0p[2][2], gp[2][2];
#pragma unroll
    for (int s = 0; s < 2; s++) {
        int base = prb + s * 16;
        A1[s][0] = g_vf[n][four][base];
        A1[s][1] = g_vf[n][four][base + 8];
        A2[s][0] = g_sp16[n][four][base];
        A2[s][1] = g_sp16[n][four][base + 8];
        A2[s][2] = g_sp16[n][four + 4][base];
        A2[s][3] = g_sp16[n][four + 4][base + 8];
        A3[s][0] = g_sp16[n][8 + four][base];
        A3[s][1] = g_sp16[n][8 + four][base + 8];
        a0p[s][0] = g_a0v[n][base];
        a0p[s][1] = g_a0v[n][base + 8];
        gp[s][0]  = g_gate[n][base];
        gp[s][1]  = g_gate[n][base + 8];
    }

    // 4 independent accumulators: index = s*2 + d-row
    float acc[4] = {0.f, 0.f, 0.f, 0.f};

#pragma unroll 4
    for (int chunk = 0; chunk < TS / 8; chunk++) {
        int qc = chunk * 8;
        int qb = qc + g;
        uint32_t b1  = sfeat[four][qb];
        uint32_t b2a = sseg[four][qb];
        uint32_t b2b = sseg[four + 4][qb];
        uint32_t b2c = sseg[8 + four][qb];
        int c0 = qc + 2 * four;
        float4 ag = *(const float4*)&sa0g[2 * c0];   // a0q0, gq0', a0q1, gq1'

#pragma unroll
        for (int s = 0; s < 2; s++) {
            float d1[4];
            d1[0] = a0p[s][0] + ag.x;
            d1[1] = a0p[s][0] + ag.z;
            d1[2] = a0p[s][1] + ag.x;
            d1[3] = a0p[s][1] + ag.z;
            mma_k8(d1, A1[s][0], A1[s][1], b1);

            float d2[4] = {0.f, 0.f, 0.f, 0.f};
            mma_k16(d2, A2[s][0], A2[s][1], A2[s][2], A2[s][3], b2a, b2b);
            mma_k8(d2, A3[s][0], A3[s][1], b2c);

            float w00 = ex2(d1[0]);
            float w01 = ex2(d1[1]);
            float w10 = ex2(d1[2]);
            float w11 = ex2(d1[3]);
            acc[s * 2 + 0] = fmaf(w00 * d2[0], gp[s][0] + ag.y, acc[s * 2 + 0]);
            acc[s * 2 + 0] = fmaf(w01 * d2[1], gp[s][0] + ag.w, acc[s * 2 + 0]);
            acc[s * 2 + 1] = fmaf(w10 * d2[2], gp[s][1] + ag.y, acc[s * 2 + 1]);
            acc[s * 2 + 1] = fmaf(w11 * d2[3], gp[s][1] + ag.w, acc[s * 2 + 1]);
        }
    }

    float accs = (acc[0] + acc[1]) + (acc[2] + acc[3]);

#pragma unroll
    for (int o = 16; o > 0; o >>= 1)
        accs += __shfl_down_sync(0xffffffffu, accs, o);
    if (lane == 0) red[w] = accs;
    __syncthreads();
    if (t == 0) {
        float s = 0.0f;
#pragma unroll
        for (int i = 0; i < 8; i++) s += red[i];
        g_part[(size_t)n * NTRI + blockIdx.x] = s;
        __threadfence();
        int old = atomicAdd(&g_cnt, 1);
        isLast = (old == NBLK - 1);
    }
    __syncthreads();

    if (isLast && t < 32) {
        __threadfence();
        float v = 0.0f;
        for (int i = t; i < NBLK; i += 32) v += g_part[i];
#pragma unroll
        for (int o = 16; o > 0; o >>= 1)
            v += __shfl_down_sync(0xffffffffu, v, o);
        if (t == 0) {
            out[0] = v * (-0.05f / 16384.0f);
            g_cnt = 0;
        }
    }
}

extern "C" void kernel_launch(void* const* d_in, const int* in_sizes, int n_in,
                              void* d_out, int out_size) {
    const float* img = (const float*)d_in[0];
    const float* seg = (const float*)d_in[1];
    const float* roi = (const float*)d_in[2];
    const float* lab = (const float*)d_in[3];
    float* out = (float*)d_out;

    prep1_kernel<<<(NB * KP * 2048) / 256, 256>>>(seg, roi);
    prep2_kernel<<<(NB * PTOT) / 128, 128>>>(img, roi, lab);
    dim3 grid(NTRI, 1, NB);
    pair_kernel<<<grid, 256>>>(out);
}

// round 14
// speedup vs baseline: 6.1555x; 1.0511x over previous
#include <cuda_runtime.h>
#include <cuda_fp16.h>
#include <stdint.h>

// DenseEnergyLoss: fp16 tensor-core GEMMs + fp32 exp epilogue.
// arg = a0v(p) + [v,1,1].[u, a0hi, a0fine] (MMA, fp32 accum)  ~= -0.5*d2*log2e
// out = -0.05 * S / 16384

#define NB   4
#define KC   21
#define HH   128
#define WW   128
#define PTOT 4096
#define TS   256
#define NPT  (PTOT/TS)          // 16
#define NTRI (NPT*(NPT+1)/2)    // 136
#define NBLK (NTRI*NB)          // 544 work items
#define GRID 444                // 148 SMs * 3 resident blocks
#define KP   11

#define LOG2E 1.4426950408889634f
#define SPAD  264

__device__ uint32_t g_sp16[NB][12][PTOT];  // half2 seg*roi k-pairs (row 11 zero)
__device__ uint32_t g_vf  [NB][4][PTOT];   // A-side: (v0,v1)(v2,v3)(v4,1)(1,0)
__device__ uint32_t g_uf  [NB][4][PTOT];   // B-side: (u0,u1)(u2,u3)(u4,a0hi)(a0fine,0)
__device__ float    g_a0v [NB][PTOT];
__device__ float    g_gate[NB][PTOT];
__device__ float    g_part[NBLK];
__device__ int      g_cnt;                 // zero-init; last block resets
__device__ int      g_work;                // zero-init; last block resets

__device__ __forceinline__ float ex2(float x) {
    float y; asm("ex2.approx.f32 %0, %1;" : "=f"(y) : "f"(x)); return y;
}
__device__ __forceinline__ uint32_t h2(float a, float b) {
    __half2 h = __floats2half2_rn(a, b);
    return *(uint32_t*)&h;
}
__device__ __forceinline__ void mma_k16(float d[4],
    uint32_t a0, uint32_t a1, uint32_t a2, uint32_t a3,
    uint32_t b0, uint32_t b1) {
    asm volatile("mma.sync.aligned.m16n8k16.row.col.f32.f16.f16.f32 "
        "{%0,%1,%2,%3}, {%4,%5,%6,%7}, {%8,%9}, {%0,%1,%2,%3};"
        : "+f"(d[0]), "+f"(d[1]), "+f"(d[2]), "+f"(d[3])
        : "r"(a0), "r"(a1), "r"(a2), "r"(a3), "r"(b0), "r"(b1));
}
__device__ __forceinline__ void mma_k8(float d[4],
    uint32_t a0, uint32_t a1, uint32_t b0) {
    asm volatile("mma.sync.aligned.m16n8k8.row.col.f32.f16.f16.f32 "
        "{%0,%1,%2,%3}, {%4,%5}, {%6}, {%0,%1,%2,%3};"
        : "+f"(d[0]), "+f"(d[1]), "+f"(d[2]), "+f"(d[3])
        : "r"(a0), "r"(a1), "r"(b0));
}

// ---------------------------------------------------------------------------
// Phase 1a: fused downsample + roi multiply + fp16 k-pair pack.
// ---------------------------------------------------------------------------
__global__ void prep1_kernel(const float* __restrict__ seg,
                             const float* __restrict__ roi) {
    int idx = blockIdx.x * blockDim.x + threadIdx.x;   // NB*KP*2048
    int n = idx / (KP * 2048);
    int rem = idx - n * (KP * 2048);
    int kp = rem >> 11;
    int pq = rem & 2047;
    int p = pq << 1;
    int y = p >> 6, x = p & 63;
    int k0 = 2 * kp;

    const float4* s0 = (const float4*)(seg + (((size_t)(n * KC + k0) * HH + 2 * y) * WW + 2 * x));
    float4 a0 = s0[0];
    float4 b0 = s0[WW / 4];

    const float4* rr = (const float4*)(roi + ((size_t)n * HH + 2 * y) * WW + 2 * x);
    float4 r0 = rr[0];
    float rv0 = r0.x, rv1 = r0.z;

    float sA0 = 0.25f * (a0.x + a0.y + b0.x + b0.y);
    float sA1 = 0.25f * (a0.z + a0.w + b0.z + b0.w);

    float sB0 = 0.0f, sB1 = 0.0f;
    if (kp < 10) {
        const float4* s1 = (const float4*)(seg + (((size_t)(n * KC + k0 + 1) * HH + 2 * y) * WW + 2 * x));
        float4 c0 = s1[0];
        float4 d0 = s1[WW / 4];
        sB0 = 0.25f * (c0.x + c0.y + d0.x + d0.y);
        sB1 = 0.25f * (c0.z + c0.w + d0.z + d0.w);
    }

    uint2 outw;
    outw.x = h2(sA0 * rv0, sB0 * rv0);
    outw.y = h2(sA1 * rv1, sB1 * rv1);
    *(uint2*)&g_sp16[n][kp][p] = outw;
}

// ---------------------------------------------------------------------------
// Phase 1b: gate, features, a0 terms (a0u split hi/fine into fp16 B slots).
// ---------------------------------------------------------------------------
__global__ void prep2_kernel(const float* __restrict__ img,
                             const float* __restrict__ roi,
                             const float* __restrict__ lab) {
    int idx = blockIdx.x * blockDim.x + threadIdx.x;   // NB*PTOT
    int n = idx >> 12;
    int p = idx & (PTOT - 1);
    int y = p >> 6, x = p & 63;
    int yy = 2 * y, xx = 2 * x;

    __half2 hmax = __floats2half2_rn(0.0f, 0.0f);
#pragma unroll
    for (int kp = 0; kp < KP; kp++) {
        uint32_t m = g_sp16[n][kp][p];
        hmax = __hmax2(hmax, *(__half2*)&m);
    }
    float mx = fmaxf(__low2float(hmax), __high2float(hmax));

    float r  = roi[((size_t)n * HH + yy) * WW + xx];
    float lv = lab[((size_t)n * HH + yy) * WW + xx];
    float inv = (r > 0.0f) ? __frcp_rn(r) : 0.0f;
    float gate = ((int)lv == 255) ? 1.0f : (r - mx * inv);
    g_gate[n][p] = fmaxf(gate, 0.0f);

    float f[5];
    f[0] = (float)x * (1.0f / 40.0f);
    f[1] = (float)y * (1.0f / 40.0f);
    f[2] = img[(((size_t)(n * 3 + 0)) * HH + yy) * WW + xx] * (1.0f / 15.0f);
    f[3] = img[(((size_t)(n * 3 + 1)) * HH + yy) * WW + xx] * (1.0f / 15.0f);
    f[4] = img[(((size_t)(n * 3 + 2)) * HH + yy) * WW + xx] * (1.0f / 15.0f);

    float sv = 0.0f, su = 0.0f, vr[5], ur[5];
#pragma unroll
    for (int c = 0; c < 5; c++) {
        vr[c] = __half2float(__float2half(f[c]));
        ur[c] = __half2float(__float2half(LOG2E * f[c]));
        sv += vr[c] * vr[c];
        su += ur[c] * ur[c];
    }
    g_a0v[n][p] = -0.5f * LOG2E * sv;
    float a0u = (-0.5f / LOG2E) * su;
    float a0hi_f = __half2float(__float2half_rn(a0u));
    float a0fine = a0u - a0hi_f;        // exact (Sterbenz)

    g_vf[n][0][p] = h2(vr[0], vr[1]);
    g_vf[n][1][p] = h2(vr[2], vr[3]);
    g_vf[n][2][p] = h2(vr[4], 1.0f);
    g_vf[n][3][p] = h2(1.0f, 0.0f);
    g_uf[n][0][p] = h2(ur[0], ur[1]);
    g_uf[n][1][p] = h2(ur[2], ur[3]);
    g_uf[n][2][p] = h2(ur[4], a0hi_f);
    g_uf[n][3][p] = h2(a0fine, 0.0f);
}

// ---------------------------------------------------------------------------
// Phase 2: persistent work-stealing tile-pair kernel. 256 thr, 3 blocks/SM.
// Per chunk: d1 MMA (k8, carries a0u), d2a (k16) + d2b (k8) independent.
// ---------------------------------------------------------------------------
__global__ __launch_bounds__(256, 3) void pair_kernel(float* __restrict__ out) {
    __shared__ uint32_t sseg[12][SPAD];
    __shared__ uint32_t sfeat[4][SPAD];
    __shared__ __align__(8) float sg[TS];
    __shared__ float red[8];
    __shared__ int s_idx;
    __shared__ int isLast;

    int t = threadIdx.x;
    int w = t >> 5, lane = t & 31;
    int g = lane >> 2, four = lane & 3;

    sseg[11][t >= TS ? 0 : t] = 0u;   // row 11 constant zero (t<256 always)

    while (true) {
        if (t == 0) s_idx = atomicAdd(&g_work, 1);
        __syncthreads();              // publishes s_idx; guards smem reuse
        int widx = s_idx;
        if (widx >= NBLK) break;

        int n = widx / NTRI;
        int tri = widx - n * NTRI;
        int bp = 0;
        while (tri >= NPT - bp) { tri -= NPT - bp; bp++; }
        int bq = bp + tri;
        float offd = (bp == bq) ? 0.0f : 1.0f;

        int p0 = bp * TS, q0 = bq * TS;

#pragma unroll
        for (int kp = 0; kp < KP; kp++) sseg[kp][t] = g_sp16[n][kp][q0 + t];
#pragma unroll
        for (int c = 0; c < 4; c++) sfeat[c][t] = g_uf[n][c][q0 + t];
        sg[t] = g_gate[n][q0 + t] * offd;
        __syncthreads();

        int prb = p0 + w * 32 + g;

        uint32_t A1[2][2], A2[2][4], A3[2][2];
        float a0p[2][2], gp[2][2];
#pragma unroll
        for (int s = 0; s < 2; s++) {
            int base = prb + s * 16;
            A1[s][0] = g_vf[n][four][base];
            A1[s][1] = g_vf[n][four][base + 8];
            A2[s][0] = g_sp16[n][four][base];
            A2[s][1] = g_sp16[n][four][base + 8];
            A2[s][2] = g_sp16[n][four + 4][base];
            A2[s][3] = g_sp16[n][four + 4][base + 8];
            A3[s][0] = g_sp16[n][8 + four][base];
            A3[s][1] = g_sp16[n][8 + four][base + 8];
            a0p[s][0] = g_a0v[n][base];
            a0p[s][1] = g_a0v[n][base + 8];
            gp[s][0]  = g_gate[n][base];
            gp[s][1]  = g_gate[n][base + 8];
        }

        float acc[4] = {0.f, 0.f, 0.f, 0.f};

#pragma unroll 4
        for (int chunk = 0; chunk < TS / 8; chunk++) {
            int qc = chunk * 8;
            int qb = qc + g;
            uint32_t b1a = sfeat[four][qb];
            uint32_t b2a = sseg[four][qb];
            uint32_t b2b = sseg[four + 4][qb];
            uint32_t b2c = sseg[8 + four][qb];
            int c0 = qc + 2 * four;
            float2 gq = *(const float2*)&sg[c0];

#pragma unroll
            for (int s = 0; s < 2; s++) {
                float d1[4];
                d1[0] = a0p[s][0];
                d1[1] = a0p[s][0];
                d1[2] = a0p[s][1];
                d1[3] = a0p[s][1];
                mma_k8(d1, A1[s][0], A1[s][1], b1a);   // + v.u + a0hi + a0fine

                float d2a[4] = {0.f, 0.f, 0.f, 0.f};
                float d2b[4] = {0.f, 0.f, 0.f, 0.f};
                mma_k16(d2a, A2[s][0], A2[s][1], A2[s][2], A2[s][3], b2a, b2b);
                mma_k8(d2b, A3[s][0], A3[s][1], b2c);

                float w00 = ex2(d1[0]);
                float w01 = ex2(d1[1]);
                float w10 = ex2(d1[2]);
                float w11 = ex2(d1[3]);
                acc[s * 2 + 0] = fmaf(w00 * (d2a[0] + d2b[0]), gp[s][0] + gq.x, acc[s * 2 + 0]);
                acc[s * 2 + 0] = fmaf(w01 * (d2a[1] + d2b[1]), gp[s][0] + gq.y, acc[s * 2 + 0]);
                acc[s * 2 + 1] = fmaf(w10 * (d2a[2] + d2b[2]), gp[s][1] + gq.x, acc[s * 2 + 1]);
                acc[s * 2 + 1] = fmaf(w11 * (d2a[3] + d2b[3]), gp[s][1] + gq.y, acc[s * 2 + 1]);
            }
        }

        float accs = (acc[0] + acc[1]) + (acc[2] + acc[3]);

#pragma unroll
        for (int o = 16; o > 0; o >>= 1)
            accs += __shfl_down_sync(0xffffffffu, accs, o);
        if (lane == 0) red[w] = accs;
        __syncthreads();
        if (t == 0) {
            float s = 0.0f;
#pragma unroll
            for (int i = 0; i < 8; i++) s += red[i];
            g_part[widx] = s;
        }
        // loop-top __syncthreads guards smem restage
    }

    if (t == 0) {
        __threadfence();
        int old = atomicAdd(&g_cnt, 1);
        isLast = (old == GRID - 1);
    }
    __syncthreads();

    if (isLast && t < 32) {
        __threadfence();
        float v = 0.0f;
        for (int i = t; i < NBLK; i += 32) v += g_part[i];
#pragma unroll
        for (int o = 16; o > 0; o >>= 1)
            v += __shfl_down_sync(0xffffffffu, v, o);
        if (t == 0) {
            out[0] = v * (-0.05f / 16384.0f);
            g_cnt = 0;
            g_work = 0;
        }
    }
}

extern "C" void kernel_launch(void* const* d_in, const int* in_sizes, int n_in,
                              void* d_out, int out_size) {
    const float* img = (const float*)d_in[0];
    const float* seg = (const float*)d_in[1];
    const float* roi = (const float*)d_in[2];
    const float* lab = (const float*)d_in[3];
    float* out = (float*)d_out;

    prep1_kernel<<<(NB * KP * 2048) / 256, 256>>>(seg, roi);
    prep2_kernel<<<(NB * PTOT) / 128, 128>>>(img, roi, lab);
    pair_kernel<<<GRID, 256>>>(out);
}